// round 16
// baseline (speedup 1.0000x reference)
#include <cuda_runtime.h>
#include <cuda_pipeline.h>
#include <math.h>

#define NIMG 4
#define NCLS 19
#define HWPIX 589824            // 768*768
#define NTOT (NIMG * HWPIX)
#define IGN 255
#define EDGE_T 0.8f
#define PPT 4                   // pixels per thread (R10-proven)
#define TPB 256
#define BPI (HWPIX / (TPB * PPT))   // 576 blocks per image
#define GRID (NIMG * BPI)           // 2304
#define INVC 31                 // "invalid" class sentinel (never matches 0..18)
#define PDEPTH 6                // cp.async prefetch depth (channels)

// ---------------- packed f32x2 helpers (sm_103a; ptxas won't auto-fuse) ----------------
__device__ __forceinline__ unsigned long long pk2(float lo, float hi) {
    unsigned long long r; asm("mov.b64 %0,{%1,%2};" : "=l"(r) : "f"(lo), "f"(hi)); return r;
}
__device__ __forceinline__ void upk2(unsigned long long v, float& lo, float& hi) {
    asm("mov.b64 {%0,%1},%2;" : "=f"(lo), "=f"(hi) : "l"(v));
}
__device__ __forceinline__ unsigned long long add2(unsigned long long a, unsigned long long b) {
    unsigned long long r; asm("add.rn.f32x2 %0,%1,%2;" : "=l"(r) : "l"(a), "l"(b)); return r;
}
__device__ __forceinline__ unsigned long long mul2(unsigned long long a, unsigned long long b) {
    unsigned long long r; asm("mul.rn.f32x2 %0,%1,%2;" : "=l"(r) : "l"(a), "l"(b)); return r;
}
__device__ __forceinline__ float ex2f(float x) {
    float r; asm("ex2.approx.ftz.f32 %0,%1;" : "=f"(r) : "f"(x)); return r;
}

// ---------------- device-global scratch (no allocations allowed) ----------------
__device__ double g_seg_sum[NIMG * NCLS];
__device__ double g_att_sum[NIMG * NCLS];
__device__ int    g_seg_cnt[NIMG * NCLS];
__device__ int    g_att_cnt[NIMG * NCLS];
__device__ double g_bce_pos, g_bce_neg;
__device__ int    g_pos, g_neg;
__device__ unsigned g_done;

// ---------------- single fused kernel (R10 base, issue-slimmed) ----------------
__global__ void __launch_bounds__(TPB) k_fused(const float* __restrict__ segin,
                                               const float* __restrict__ edgein,
                                               const int* __restrict__ segmask,
                                               const int* __restrict__ emask,
                                               float* __restrict__ out) {
    __shared__ float4 pbuf[PDEPTH][TPB];     // 24 KB prefetch ring (per-thread slots)
    __shared__ float  sh_ss[NCLS][64];       // 8 warps x 8 partials per class
    __shared__ float  sh_sa[NCLS][64];
    __shared__ unsigned sh_cc[NCLS][8];
    __shared__ float  sh_bp[8], sh_bn[8];
    __shared__ unsigned sh_pn[8];

    int n   = blockIdx.x / BPI;
    int tid = threadIdx.x;
    int wid = tid >> 5;
    int lid = tid & 31;

    int local = (blockIdx.x % BPI) * (TPB * PPT) + tid * PPT;
    int p     = n * HWPIX + local;

    const float* sp = segin + (size_t)n * (size_t)NCLS * (size_t)HWPIX + (size_t)local;

    // kick off the segin pipeline FIRST so DRAM is busy during the prologue
#pragma unroll
    for (int c = 0; c < PDEPTH; c++) {
        __pipeline_memcpy_async(&pbuf[c][tid], sp + (size_t)c * HWPIX, 16);
        __pipeline_commit();
    }

    // ---- prologue: masks + BCE ----
    int4   t4 = *(const int4*)(segmask + p);
    float4 e4 = *(const float4*)(edgein + p);
    int4   m4 = *(const int4*)(emask + p);

    int   tv[PPT] = {t4.x, t4.y, t4.z, t4.w};
    float ev[PPT] = {e4.x, e4.y, e4.z, e4.w};
    int   mv[PPT] = {m4.x, m4.y, m4.z, m4.w};

    int tcls[PPT];               // class for select; INVC for ignored pixels
    unsigned attb = 0u;
    float bce_p = 0.f, bce_n = 0.f;
    unsigned pn = 0;             // pos lo16, neg hi16
#pragma unroll
    for (int i = 0; i < PPT; i++) {
        bool v  = (tv[i] != IGN);
        tcls[i] = v ? min(max(tv[i], 0), NCLS - 1) : INVC;
        if (v && (ev[i] > EDGE_T)) attb |= (1u << i);

        float xx = ev[i];
        float b  = fmaxf(xx, 0.f) - xx * (float)mv[i] + log1pf(__expf(-fabsf(xx)));
        if (mv[i] == 1) { bce_p += b; pn += 1u; }
        else if (mv[i] == 0) { bce_n += b; pn += 0x10000u; }
    }

    // ---- channel sweep out of the SMEM ring (packed f32x2 mul/add) ----
    const unsigned long long L2E2 = pk2(1.4426950408889634f, 1.4426950408889634f);
    unsigned long long s01 = 0ull, s23 = 0ull;   // packed {0.f,0.f}
    float xt[PPT];
#pragma unroll
    for (int i = 0; i < PPT; i++) xt[i] = 0.f;

#pragma unroll
    for (int c = 0; c < NCLS; c++) {
        __pipeline_wait_prior(PDEPTH - 1);        // channel c's copy has landed
        float4 x = pbuf[c % PDEPTH][tid];
        int cn = c + PDEPTH;
        if (cn < NCLS)
            __pipeline_memcpy_async(&pbuf[c % PDEPTH][tid], sp + (size_t)cn * HWPIX, 16);
        __pipeline_commit();                      // keep group numbering uniform

        // exp via packed pre-scale + scalar EX2 (MUFU is scalar-only)
        unsigned long long a01 = mul2(pk2(x.x, x.y), L2E2);
        unsigned long long a23 = mul2(pk2(x.z, x.w), L2E2);
        float b0, b1, b2, b3;
        upk2(a01, b0, b1); upk2(a23, b2, b3);
        s01 = add2(s01, pk2(ex2f(b0), ex2f(b1)));
        s23 = add2(s23, pk2(ex2f(b2), ex2f(b3)));

        xt[0] = (c == tcls[0]) ? x.x : xt[0];
        xt[1] = (c == tcls[1]) ? x.y : xt[1];
        xt[2] = (c == tcls[2]) ? x.z : xt[2];
        xt[3] = (c == tcls[3]) ? x.w : xt[3];
    }

    float s[PPT];
    upk2(s01, s[0], s[1]);
    upk2(s23, s[2], s[3]);

    // ---- per-pixel nll ----
    float nll[PPT], nllA[PPT];
    unsigned addC[PPT];
#pragma unroll
    for (int i = 0; i < PPT; i++) {
        nll[i]  = __logf(s[i]) - xt[i];          // -log_softmax[target]
        bool a  = (attb >> i) & 1u;
        nllA[i] = a ? nll[i] : 0.f;
        addC[i] = a ? 0x10001u : 1u;             // att cnt hi16, seg cnt lo16
    }

    // ---- per-class select + 2-level shuffle (8 partials/warp) ----
#pragma unroll
    for (int c = 0; c < NCLS; c++) {
        float ss = 0.f, sa = 0.f;
        unsigned cc = 0u;
#pragma unroll
        for (int i = 0; i < PPT; i++) {
            if (tcls[i] == c) { ss += nll[i]; sa += nllA[i]; cc += addC[i]; }
        }
        ss += __shfl_down_sync(0xffffffffu, ss, 16);
        ss += __shfl_down_sync(0xffffffffu, ss, 8);
        sa += __shfl_down_sync(0xffffffffu, sa, 16);
        sa += __shfl_down_sync(0xffffffffu, sa, 8);
        cc = __reduce_add_sync(0xffffffffu, cc);
        if (lid < 8) { sh_ss[c][wid * 8 + lid] = ss; sh_sa[c][wid * 8 + lid] = sa; }
        if (lid == 0) sh_cc[c][wid] = cc;
    }
    for (int o = 16; o; o >>= 1) {
        bce_p += __shfl_down_sync(0xffffffffu, bce_p, o);
        bce_n += __shfl_down_sync(0xffffffffu, bce_n, o);
    }
    pn = __reduce_add_sync(0xffffffffu, pn);
    if (lid == 0) { sh_bp[wid] = bce_p; sh_bn[wid] = bce_n; sh_pn[wid] = pn; }
    __syncthreads();

    // ---- block combine (64 partials per class) + global accumulation ----
    if (tid < NCLS) {
        float ss = 0.f, sa = 0.f; unsigned cc = 0u;
#pragma unroll
        for (int w = 0; w < 64; w++) { ss += sh_ss[tid][w]; sa += sh_sa[tid][w]; }
#pragma unroll
        for (int w = 0; w < 8; w++) cc += sh_cc[tid][w];
        int gi = n * NCLS + tid;
        atomicAdd(&g_seg_sum[gi], (double)ss);
        atomicAdd(&g_att_sum[gi], (double)sa);
        atomicAdd(&g_seg_cnt[gi], (int)(cc & 0xffffu));
        atomicAdd(&g_att_cnt[gi], (int)(cc >> 16));
    } else if (tid == 32) {
        float bp = 0.f, bn = 0.f; unsigned c = 0u;
#pragma unroll
        for (int w = 0; w < 8; w++) { bp += sh_bp[w]; bn += sh_bn[w]; c += sh_pn[w]; }
        atomicAdd(&g_bce_pos, (double)bp);
        atomicAdd(&g_bce_neg, (double)bn);
        atomicAdd(&g_pos, (int)(c & 0xffffu));
        atomicAdd(&g_neg, (int)(c >> 16));
    }

    // ---- fan-in: last block finalizes ----
    __syncthreads();
    __shared__ unsigned s_last;
    if (tid == 0) {
        __threadfence();
        s_last = (atomicAdd(&g_done, 1u) == GRID - 1u);
    }
    __syncthreads();
    if (!s_last) return;
    __threadfence();   // acquire: make all blocks' g_* writes visible

    // ---------------- finalize (parallel, division-light) ----------------
    __shared__ double f_ss[NIMG * NCLS], f_as[NIMG * NCLS];
    __shared__ int    f_sc[NIMG * NCLS], f_ac[NIMG * NCLS];
    __shared__ double f_rs[NIMG], f_ra[NIMG];
    __shared__ double f_t[NIMG * NCLS][4];
    __shared__ double f_img[NIMG][2];
    __shared__ double f_bce[2];
    __shared__ int    f_pn[2];

    if (tid < NIMG * NCLS) {
        f_ss[tid] = g_seg_sum[tid];
        f_as[tid] = g_att_sum[tid];
        f_sc[tid] = g_seg_cnt[tid];
        f_ac[tid] = g_att_cnt[tid];
    }
    if (tid == 96) { f_bce[0] = g_bce_pos; f_bce[1] = g_bce_neg; }
    if (tid == 97) { f_pn[0] = g_pos; f_pn[1] = g_neg; }
    __syncthreads();

    if (tid < NIMG) {
        int ssum = 0, asum = 0;
#pragma unroll
        for (int c = 0; c < NCLS; c++) { ssum += f_sc[tid * NCLS + c]; asum += f_ac[tid * NCLS + c]; }
        f_rs[tid] = 1.0 / (double)ssum;
        f_ra[tid] = 1.0 / (double)asum;
    }
    __syncthreads();

    if (tid < NIMG * NCLS) {
        int nimg = tid / NCLS;
        int sc = f_sc[tid], ac = f_ac[tid];
        double ws = sc ? (2.0 - (double)sc * f_rs[nimg]) : 1.0;
        double wa = ac ? (2.0 - (double)ac * f_ra[nimg]) : 1.0;
        f_t[tid][0] = ws * f_ss[tid];
        f_t[tid][1] = ws * (double)sc;
        f_t[tid][2] = wa * f_as[tid];
        f_t[tid][3] = wa * (double)ac;
    }
    __syncthreads();

    if (tid < NIMG) {
        double sn = 0, sd = 0, an = 0, ad = 0;
#pragma unroll
        for (int c = 0; c < NCLS; c++) {
            sn += f_t[tid * NCLS + c][0]; sd += f_t[tid * NCLS + c][1];
            an += f_t[tid * NCLS + c][2]; ad += f_t[tid * NCLS + c][3];
        }
        f_img[tid][0] = sn / sd;
        f_img[tid][1] = an / ad;
    }
    __syncthreads();

    if (tid == 0) {
        double segl = 0.0, attl = 0.0;
#pragma unroll
        for (int nn2 = 0; nn2 < NIMG; nn2++) { segl += f_img[nn2][0]; attl += f_img[nn2][1]; }
        double pp = (double)f_pn[0], nng = (double)f_pn[1], sm = pp + nng;
        double bce = ((nng / sm) * f_bce[0] + (pp / sm) * f_bce[1]) / (double)NTOT;
        out[0] = (float)(segl + 0.3 * bce + 0.1 * attl);
    }

    // reset scratch for next graph replay
    if (tid < NIMG * NCLS) {
        g_seg_sum[tid] = 0.0; g_att_sum[tid] = 0.0;
        g_seg_cnt[tid] = 0;   g_att_cnt[tid] = 0;
    }
    if (tid == 96) { g_bce_pos = 0.0; g_bce_neg = 0.0; }
    if (tid == 97) { g_pos = 0; g_neg = 0; }
    if (tid == 98) g_done = 0u;
}

extern "C" void kernel_launch(void* const* d_in, const int* in_sizes, int n_in,
                              void* d_out, int out_size) {
    const float* segin   = (const float*)d_in[0];
    const float* edgein  = (const float*)d_in[1];
    const int*   segmask = (const int*)d_in[2];
    const int*   emask   = (const int*)d_in[3];

    k_fused<<<GRID, TPB>>>(segin, edgein, segmask, emask, (float*)d_out);
}